// round 4
// baseline (speedup 1.0000x reference)
#include <cuda_runtime.h>

#define HH 4
#define BB 32
#define NNODE 14
#define FF 1024
#define NF (NNODE*FF)   // 14336

#define ALPHA_SLOPE 0.2f
#define NEGV (-9000000000000000.0f)

// Scratch (no allocation allowed): 7MB + 7MB + 4MB
static __device__ float g_Wh[HH*BB*NNODE*FF];
static __device__ float g_hp[HH*BB*NNODE*FF];
static __device__ float g_part[32*BB*FF];

// ---- packed fp32x2 helpers (Blackwell FFMA2 pipe, PTX-only) ----
__device__ __forceinline__ unsigned long long pk2(float a, float b){
    unsigned long long r;
    asm("mov.b64 %0, {%1, %2};" : "=l"(r) : "f"(a), "f"(b));
    return r;
}
__device__ __forceinline__ void fma2(unsigned long long &d, unsigned long long a, unsigned long long b){
    asm("fma.rn.f32x2 %0, %1, %2, %0;" : "+l"(d) : "l"(a), "l"(b));
}
__device__ __forceinline__ float2 upk(unsigned long long v){
    float2 r;
    asm("mov.b64 {%0, %1}, %2;" : "=f"(r.x), "=f"(r.y) : "l"(v));
    return r;
}

// ============================================================================
// K1: Wh[h,b,n,o] = sum_i x[b,n,i] * W[h,b,i,o]
// One block per (h,b). 256 threads, each owns 4 consecutive o columns.
// x row-block staged in smem (broadcast reads), W streamed coalesced.
// ============================================================================
__global__ __launch_bounds__(256) void k1_wh(const float* __restrict__ x,
                                             const float* __restrict__ W){
    const int hb  = blockIdx.x;          // h*BB + b
    const int b   = hb & (BB-1);
    const int tid = threadIdx.x;

    const float* xb = x + (size_t)b * NNODE * FF;
    const float* Wp = W + (size_t)hb * FF * FF;

    __shared__ __align__(16) float sx[NNODE*512];

    unsigned long long acc[NNODE][2];
#pragma unroll
    for(int n=0;n<NNODE;n++){ acc[n][0]=0ull; acc[n][1]=0ull; }

    for(int kc=0;kc<2;kc++){
        __syncthreads();
        for(int i=tid;i<NNODE*512;i+=256){
            int n = i >> 9, kk = i & 511;
            sx[i] = xb[n*FF + kc*512 + kk];
        }
        __syncthreads();

        const float4* wrow = (const float4*)(Wp + (size_t)kc*512*FF) + tid;
#pragma unroll 4
        for(int kk=0;kk<512;kk++){
            float4 w = wrow[(size_t)kk*(FF/4)];
            unsigned long long w01 = pk2(w.x,w.y);
            unsigned long long w23 = pk2(w.z,w.w);
#pragma unroll
            for(int n=0;n<NNODE;n++){
                float xv = sx[(n<<9)+kk];
                unsigned long long xp = pk2(xv,xv);
                fma2(acc[n][0], xp, w01);
                fma2(acc[n][1], xp, w23);
            }
        }
    }

    float* out = g_Wh + (size_t)hb * NF + tid*4;
#pragma unroll
    for(int n=0;n<NNODE;n++){
        float2 a0 = upk(acc[n][0]);
        float2 a1 = upk(acc[n][1]);
        *(float4*)(out + (size_t)n*FF) = make_float4(a0.x,a0.y,a1.x,a1.y);
    }
}

// ============================================================================
// K2: per (h,b): s1[n]=Wh[n,:]·a1, s2[n]=Wh[n,:]·a2,
//     e[n,m]=lrelu(s1[n]+s2[m]); att=softmax over n of where(adj>0,e,NEG);
//     h_prime[n,o] = sum_m att[n,m] * Wh[m,o]
// ============================================================================
__global__ __launch_bounds__(256) void k2_att(const float* __restrict__ adj,
                                              const float* __restrict__ a){
    const int hb  = blockIdx.x;
    const int b   = hb & (BB-1);
    const int tid = threadIdx.x;

    const float* Wh = g_Wh + (size_t)hb * NF;
    const float* av = a + (size_t)hb * 2 * FF;

    __shared__ float s_s1[NNODE], s_s2[NNODE];
    __shared__ float satt[NNODE][NNODE];
    __shared__ float red[2*NNODE][8];

    // ---- phase A: s1, s2 ----
    float p1[NNODE], p2[NNODE];
#pragma unroll
    for(int n=0;n<NNODE;n++){ p1[n]=0.f; p2[n]=0.f; }

#pragma unroll
    for(int oi=0;oi<4;oi++){
        int o = tid + oi*256;
        float a1v = av[o];
        float a2v = av[FF + o];
#pragma unroll
        for(int n=0;n<NNODE;n++){
            float w = Wh[(size_t)n*FF + o];
            p1[n] += w*a1v;
            p2[n] += w*a2v;
        }
    }
#pragma unroll
    for(int n=0;n<NNODE;n++){
#pragma unroll
        for(int off=16;off;off>>=1){
            p1[n] += __shfl_xor_sync(0xFFFFFFFFu, p1[n], off);
            p2[n] += __shfl_xor_sync(0xFFFFFFFFu, p2[n], off);
        }
    }
    int wid = tid>>5, lid = tid&31;
    if(lid==0){
#pragma unroll
        for(int n=0;n<NNODE;n++){ red[n][wid]=p1[n]; red[NNODE+n][wid]=p2[n]; }
    }
    __syncthreads();
    if(tid < 2*NNODE){
        float s=0.f;
#pragma unroll
        for(int w=0;w<8;w++) s += red[tid][w];
        if(tid < NNODE) s_s1[tid] = s; else s_s2[tid-NNODE] = s;
    }
    __syncthreads();

    // ---- phase B: attention column m, softmax over n ----
    if(tid < NNODE){
        int m = tid;
        float col[NNODE];
        float mx = -3.4e38f;
#pragma unroll
        for(int n=0;n<NNODE;n++){
            float e = s_s1[n] + s_s2[m];
            e = (e > 0.f) ? e : ALPHA_SLOPE*e;
            float v = (adj[(size_t)b*NNODE*NNODE + n*NNODE + m] > 0.f) ? e : NEGV;
            col[n] = v;
            mx = fmaxf(mx, v);
        }
        float sum = 0.f;
#pragma unroll
        for(int n=0;n<NNODE;n++){
            col[n] = expf(col[n]-mx);
            sum += col[n];
        }
        float inv = 1.f/sum;
#pragma unroll
        for(int n=0;n<NNODE;n++) satt[n][m] = col[n]*inv;
    }
    __syncthreads();

    // ---- phase C: h_prime = att @ Wh ----
    unsigned long long acc[NNODE][2];
#pragma unroll
    for(int n=0;n<NNODE;n++){ acc[n][0]=0ull; acc[n][1]=0ull; }

    const float4* whp = (const float4*)Wh + tid;
#pragma unroll
    for(int m=0;m<NNODE;m++){
        float4 w = whp[m*(FF/4)];
        unsigned long long w01 = pk2(w.x,w.y);
        unsigned long long w23 = pk2(w.z,w.w);
#pragma unroll
        for(int n=0;n<NNODE;n++){
            float at = satt[n][m];
            unsigned long long ap = pk2(at,at);
            fma2(acc[n][0], ap, w01);
            fma2(acc[n][1], ap, w23);
        }
    }
    float* out = g_hp + (size_t)hb * NF + tid*4;
#pragma unroll
    for(int n=0;n<NNODE;n++){
        float2 a0 = upk(acc[n][0]);
        float2 a1 = upk(acc[n][1]);
        *(float4*)(out + (size_t)n*FF) = make_float4(a0.x,a0.y,a1.x,a1.y);
    }
}

// ============================================================================
// K3: split-K GEMM: part[kb][b][o] = sum_{f in chunk} hp[h,b,f]*fcw[h,o,f]
// Grid (4 o-tiles of 256, 32 k-chunks = h*8 + fchunk of 1792)
// 256 thr: thread = (og 0..63 -> 4 o's, bg 0..3 -> 8 b's). f32x2 over o-pairs.
// ============================================================================
#define KC 16
__global__ __launch_bounds__(256) void k3_fc(const float* __restrict__ fcw){
    const int ot  = blockIdx.x;       // 0..3
    const int kb  = blockIdx.y;       // 0..31
    const int h   = kb >> 3;
    const int f0  = (kb & 7) * 1792;
    const int tid = threadIdx.x;
    const int og  = tid & 63;         // o = ot*256 + og*4
    const int bg  = tid >> 6;         // b = bg*8 .. bg*8+7

    __shared__ __align__(16) float sa[KC][32];
    __shared__ __align__(16) float sb[KC][256];

    unsigned long long acc[8][2];
#pragma unroll
    for(int j=0;j<8;j++){ acc[j][0]=0ull; acc[j][1]=0ull; }

    const float* hpB = g_hp + (size_t)h * BB * NF;
    const float* wB  = fcw  + (size_t)h * FF * NF + (size_t)(ot*256) * NF;

    for(int ch=0; ch<1792/KC; ch++){
        const int fbase = f0 + ch*KC;
        __syncthreads();
        {   // stage A: 32 b x 16 f
            int i2 = tid*2;
            int bq = i2 >> 4, fq = i2 & 15;
            float2 v = *(const float2*)(hpB + (size_t)bq*NF + fbase + fq);
            sa[fq][bq] = v.x; sa[fq+1][bq] = v.y;
        }
        // stage B: 256 o x 16 f
#pragma unroll
        for(int r=0;r<4;r++){
            int idx  = tid + r*256;
            int orow = idx >> 2;
            int f4   = (idx & 3)*4;
            float4 v = *(const float4*)(wB + (size_t)orow*NF + fbase + f4);
            sb[f4  ][orow] = v.x; sb[f4+1][orow] = v.y;
            sb[f4+2][orow] = v.z; sb[f4+3][orow] = v.w;
        }
        __syncthreads();

#pragma unroll 4
        for(int k=0;k<KC;k++){
            float4 bo = *(const float4*)(&sb[k][og*4]);
            unsigned long long b01 = pk2(bo.x,bo.y);
            unsigned long long b23 = pk2(bo.z,bo.w);
            float4 av0 = *(const float4*)(&sa[k][bg*8]);
            float4 av1 = *(const float4*)(&sa[k][bg*8+4]);
            unsigned long long ap;
            ap = pk2(av0.x,av0.x); fma2(acc[0][0],ap,b01); fma2(acc[0][1],ap,b23);
            ap = pk2(av0.y,av0.y); fma2(acc[1][0],ap,b01); fma2(acc[1][1],ap,b23);
            ap = pk2(av0.z,av0.z); fma2(acc[2][0],ap,b01); fma2(acc[2][1],ap,b23);
            ap = pk2(av0.w,av0.w); fma2(acc[3][0],ap,b01); fma2(acc[3][1],ap,b23);
            ap = pk2(av1.x,av1.x); fma2(acc[4][0],ap,b01); fma2(acc[4][1],ap,b23);
            ap = pk2(av1.y,av1.y); fma2(acc[5][0],ap,b01); fma2(acc[5][1],ap,b23);
            ap = pk2(av1.z,av1.z); fma2(acc[6][0],ap,b01); fma2(acc[6][1],ap,b23);
            ap = pk2(av1.w,av1.w); fma2(acc[7][0],ap,b01); fma2(acc[7][1],ap,b23);
        }
    }

    float* pp = g_part + (size_t)kb * BB * FF + ot*256 + og*4;
#pragma unroll
    for(int j=0;j<8;j++){
        int b = bg*8 + j;
        float2 x0 = upk(acc[j][0]);
        float2 x1 = upk(acc[j][1]);
        *(float4*)(pp + (size_t)b*FF) = make_float4(x0.x,x0.y,x1.x,x1.y);
    }
}

// ============================================================================
// K4: out[b,o] = log_softmax_o( sum_kb part[kb][b][o] + sum_h fcb[h][o] )
// One block per b, 256 threads x 4 o's each.
// ============================================================================
__global__ __launch_bounds__(256) void k4_out(const float* __restrict__ fcb,
                                              float* __restrict__ out){
    const int b   = blockIdx.x;
    const int tid = threadIdx.x;
    const int wid = tid>>5, lid = tid&31;

    __shared__ float smax[8];
    __shared__ float ssum[8];

    float v[4];
#pragma unroll
    for(int j=0;j<4;j++){
        int o = tid + j*256;
        float s = 0.f;
#pragma unroll 8
        for(int kb=0;kb<32;kb++)
            s += g_part[((size_t)kb*BB + b)*FF + o];
        float bias = 0.f;
#pragma unroll
        for(int h=0;h<HH;h++) bias += fcb[h*FF + o];
        v[j] = s + bias;
    }

    float mx = fmaxf(fmaxf(v[0],v[1]), fmaxf(v[2],v[3]));
#pragma unroll
    for(int off=16;off;off>>=1) mx = fmaxf(mx, __shfl_xor_sync(0xFFFFFFFFu, mx, off));
    if(lid==0) smax[wid]=mx;
    __syncthreads();
    if(tid==0){
        float m = smax[0];
#pragma unroll
        for(int i=1;i<8;i++) m = fmaxf(m, smax[i]);
        smax[0]=m;
    }
    __syncthreads();
    float bm = smax[0];

    float s = 0.f;
#pragma unroll
    for(int j=0;j<4;j++) s += expf(v[j]-bm);
#pragma unroll
    for(int off=16;off;off>>=1) s += __shfl_xor_sync(0xFFFFFFFFu, s, off);
    if(lid==0) ssum[wid]=s;
    __syncthreads();
    if(tid==0){
        float t=0.f;
#pragma unroll
        for(int i=0;i<8;i++) t += ssum[i];
        ssum[0]=t;
    }
    __syncthreads();
    float lse = bm + logf(ssum[0]);

#pragma unroll
    for(int j=0;j<4;j++)
        out[(size_t)b*FF + tid + j*256] = v[j] - lse;
}

// ============================================================================
extern "C" void kernel_launch(void* const* d_in, const int* in_sizes, int n_in,
                              void* d_out, int out_size){
    const float* x   = (const float*)d_in[0];
    const float* adj = (const float*)d_in[1];
    const float* W   = (const float*)d_in[2];
    const float* a   = (const float*)d_in[3];
    const float* fcw = (const float*)d_in[4];
    const float* fcb = (const float*)d_in[5];
    float* out = (float*)d_out;

    k1_wh <<<HH*BB, 256>>>(x, W);
    k2_att<<<HH*BB, 256>>>(adj, a);
    k3_fc <<<dim3(4,32), 256>>>(fcw);
    k4_out<<<BB, 256>>>(fcb, out);
}

// round 5
// speedup vs baseline: 2.2962x; 2.2962x over previous
#include <cuda_runtime.h>

#define HH 4
#define BB 32
#define NNODE 14
#define FF 1024
#define NF (NNODE*FF)   // 14336

#define ALPHA_SLOPE 0.2f
#define NEGV (-9000000000000000.0f)

// Scratch (no allocation allowed)
static __device__ float g_Wh[HH*BB*NNODE*FF];   // 7 MB
static __device__ float g_hp[HH*BB*NNODE*FF];   // 7 MB
static __device__ float g_part[32*BB*FF];       // 4 MB
static __device__ float g_red[BB*FF];           // 128 KB

// ---- packed fp32x2 helpers (used only in small k2) ----
__device__ __forceinline__ unsigned long long pk2(float a, float b){
    unsigned long long r;
    asm("mov.b64 %0, {%1, %2};" : "=l"(r) : "f"(a), "f"(b));
    return r;
}
__device__ __forceinline__ void fma2(unsigned long long &d, unsigned long long a, unsigned long long b){
    asm("fma.rn.f32x2 %0, %1, %2, %0;" : "+l"(d) : "l"(a), "l"(b));
}
__device__ __forceinline__ float2 upk(unsigned long long v){
    float2 r;
    asm("mov.b64 {%0, %1}, %2;" : "=f"(r.x), "=f"(r.y) : "l"(v));
    return r;
}

// ---- cp.async helpers ----
__device__ __forceinline__ unsigned su32(const void* p){
    return (unsigned)__cvta_generic_to_shared(p);
}
__device__ __forceinline__ void cpasync16(unsigned dst, const void* src){
    asm volatile("cp.async.cg.shared.global [%0], [%1], 16;\n" :: "r"(dst), "l"(src));
}
__device__ __forceinline__ void cpcommit(){ asm volatile("cp.async.commit_group;\n" ::: "memory"); }
template<int N> __device__ __forceinline__ void cpwait(){
    asm volatile("cp.async.wait_group %0;\n" :: "n"(N) : "memory");
}

// ---- tf32 mma.sync (m16n8k8), D += A*B, fp32 accum ----
__device__ __forceinline__ void mma_tf32(float* d,
    unsigned a0, unsigned a1, unsigned a2, unsigned a3,
    unsigned b0, unsigned b1){
    asm volatile("mma.sync.aligned.m16n8k8.row.col.f32.tf32.tf32.f32 "
        "{%0,%1,%2,%3}, {%4,%5,%6,%7}, {%8,%9}, {%0,%1,%2,%3};\n"
        : "+f"(d[0]), "+f"(d[1]), "+f"(d[2]), "+f"(d[3])
        : "r"(a0), "r"(a1), "r"(a2), "r"(a3), "r"(b0), "r"(b1));
}

#define TF32_MASK 0xFFFFE000u   // keep sign+exp+top10 mantissa

// ============================================================================
// K1: Wh[h,b,:,:] (14x1024, padded M=16) = x[b] (16x1024) * W[h,b] (1024x1024)
// tf32 tensor path. A (x) split hi/lo in regs (exact); B (W) raw-f32-as-tf32.
// One block per hb; 8 warps, each owns 128 N-cols. K chunked by 16, cp.async
// double buffer. Dynamic smem: sA[16][1032] + sB[2][16][1032] = 198,144 B.
// ============================================================================
#define K1_PITCH 1032
#define K1_SMEM ((16*K1_PITCH + 2*16*K1_PITCH)*4)

__global__ __launch_bounds__(256) void k1_wh(const float* __restrict__ x,
                                             const float* __restrict__ W){
    extern __shared__ float smem[];
    float* sA = smem;                       // [16][1032]
    float* sB = smem + 16*K1_PITCH;         // [2][16][1032]

    const int hb   = blockIdx.x;
    const int b    = hb & (BB-1);
    const int tid  = threadIdx.x;
    const int lane = tid & 31;
    const int w    = tid >> 5;

    const float* xb = x + (size_t)b * NNODE * FF;
    const float* Wp = W + (size_t)hb * FF * FF;

    float acc[16][4];
#pragma unroll
    for(int j=0;j<16;j++){ acc[j][0]=0.f; acc[j][1]=0.f; acc[j][2]=0.f; acc[j][3]=0.f; }

    // prefetch B chunk 0 (16 rows x 1024 cols)
    {
        const float* src = Wp;
#pragma unroll
        for(int j=0;j<16;j++){
            int idx = tid + j*256;           // 0..4095 float4 slots
            int r   = idx >> 8;              // 0..15
            int n4  = (idx & 255) << 2;
            cpasync16(su32(&sB[(0*16 + r)*K1_PITCH + n4]), src + r*FF + n4);
        }
        cpcommit();
    }

    // stage full A (x) into smem, zero-padded to 16 rows (overlaps cp.async)
#pragma unroll
    for(int j=0;j<16;j++){
        int idx = tid + j*256;               // 4096 float4
        int r   = idx >> 8;                  // 0..15
        int k4  = (idx & 255) << 2;
        float4 v = make_float4(0.f,0.f,0.f,0.f);
        if(r < NNODE) v = *(const float4*)(xb + r*FF + k4);
        *(float4*)(&sA[r*K1_PITCH + k4]) = v;
    }

    const int ar = lane >> 2;                // A frag row group
    const int ak = lane & 3;

    for(int c=0;c<64;c++){
        const int buf = c & 1;
        if(c < 63){
            const float* src = Wp + (size_t)(c+1)*16*FF;
#pragma unroll
            for(int j=0;j<16;j++){
                int idx = tid + j*256;
                int r   = idx >> 8;
                int n4  = (idx & 255) << 2;
                cpasync16(su32(&sB[((buf^1)*16 + r)*K1_PITCH + n4]), src + r*FF + n4);
            }
            cpcommit();
            cpwait<1>();
        } else {
            cpwait<0>();
        }
        __syncthreads();

        const float* Bb = &sB[buf*16*K1_PITCH];
#pragma unroll
        for(int kh=0;kh<2;kh++){
            const int k0 = kh*8;
            const int ac = c*16 + k0 + ak;
            float a0f = sA[ar*K1_PITCH + ac];
            float a1f = sA[(ar+8)*K1_PITCH + ac];
            float a2f = sA[ar*K1_PITCH + ac + 4];
            float a3f = sA[(ar+8)*K1_PITCH + ac + 4];
            unsigned h0 = __float_as_uint(a0f) & TF32_MASK;
            unsigned h1 = __float_as_uint(a1f) & TF32_MASK;
            unsigned h2 = __float_as_uint(a2f) & TF32_MASK;
            unsigned h3 = __float_as_uint(a3f) & TF32_MASK;
            unsigned l0 = __float_as_uint(a0f - __uint_as_float(h0));
            unsigned l1 = __float_as_uint(a1f - __uint_as_float(h1));
            unsigned l2 = __float_as_uint(a2f - __uint_as_float(h2));
            unsigned l3 = __float_as_uint(a3f - __uint_as_float(h3));
#pragma unroll
            for(int j=0;j<16;j++){
                int nb = w*128 + j*8 + (lane>>2);
                unsigned b0 = __float_as_uint(Bb[(k0 + ak)*K1_PITCH + nb]);
                unsigned b1 = __float_as_uint(Bb[(k0 + ak + 4)*K1_PITCH + nb]);
                mma_tf32(acc[j], h0,h1,h2,h3, b0,b1);
                mma_tf32(acc[j], l0,l1,l2,l3, b0,b1);
            }
        }
        __syncthreads();
    }

    // store (rows < 14 only)
    float* outp = g_Wh + (size_t)hb * NF;
    const int r0 = lane >> 2;
#pragma unroll
    for(int j=0;j<16;j++){
        int col = w*128 + j*8 + 2*(lane&3);
        *(float2*)(outp + (size_t)r0*FF + col) = make_float2(acc[j][0], acc[j][1]);
        if(r0 + 8 < NNODE)
            *(float2*)(outp + (size_t)(r0+8)*FF + col) = make_float2(acc[j][2], acc[j][3]);
    }
}

// ============================================================================
// K2: per (h,b): s1[n]=Wh[n,:]·a1, s2[n]=Wh[n,:]·a2,
//     e[n,m]=lrelu(s1[n]+s2[m]); att=softmax over n of where(adj>0,e,NEG);
//     h_prime[n,o] = sum_m att[n,m] * Wh[m,o]   (unchanged, proven correct)
// ============================================================================
__global__ __launch_bounds__(256) void k2_att(const float* __restrict__ adj,
                                              const float* __restrict__ a){
    const int hb  = blockIdx.x;
    const int b   = hb & (BB-1);
    const int tid = threadIdx.x;

    const float* Wh = g_Wh + (size_t)hb * NF;
    const float* av = a + (size_t)hb * 2 * FF;

    __shared__ float s_s1[NNODE], s_s2[NNODE];
    __shared__ float satt[NNODE][NNODE];
    __shared__ float red[2*NNODE][8];

    float p1[NNODE], p2[NNODE];
#pragma unroll
    for(int n=0;n<NNODE;n++){ p1[n]=0.f; p2[n]=0.f; }

#pragma unroll
    for(int oi=0;oi<4;oi++){
        int o = tid + oi*256;
        float a1v = av[o];
        float a2v = av[FF + o];
#pragma unroll
        for(int n=0;n<NNODE;n++){
            float w = Wh[(size_t)n*FF + o];
            p1[n] += w*a1v;
            p2[n] += w*a2v;
        }
    }
#pragma unroll
    for(int n=0;n<NNODE;n++){
#pragma unroll
        for(int off=16;off;off>>=1){
            p1[n] += __shfl_xor_sync(0xFFFFFFFFu, p1[n], off);
            p2[n] += __shfl_xor_sync(0xFFFFFFFFu, p2[n], off);
        }
    }
    int wid = tid>>5, lid = tid&31;
    if(lid==0){
#pragma unroll
        for(int n=0;n<NNODE;n++){ red[n][wid]=p1[n]; red[NNODE+n][wid]=p2[n]; }
    }
    __syncthreads();
    if(tid < 2*NNODE){
        float s=0.f;
#pragma unroll
        for(int w=0;w<8;w++) s += red[tid][w];
        if(tid < NNODE) s_s1[tid] = s; else s_s2[tid-NNODE] = s;
    }
    __syncthreads();

    if(tid < NNODE){
        int m = tid;
        float col[NNODE];
        float mx = -3.4e38f;
#pragma unroll
        for(int n=0;n<NNODE;n++){
            float e = s_s1[n] + s_s2[m];
            e = (e > 0.f) ? e : ALPHA_SLOPE*e;
            float v = (adj[(size_t)b*NNODE*NNODE + n*NNODE + m] > 0.f) ? e : NEGV;
            col[n] = v;
            mx = fmaxf(mx, v);
        }
        float sum = 0.f;
#pragma unroll
        for(int n=0;n<NNODE;n++){
            col[n] = expf(col[n]-mx);
            sum += col[n];
        }
        float inv = 1.f/sum;
#pragma unroll
        for(int n=0;n<NNODE;n++) satt[n][m] = col[n]*inv;
    }
    __syncthreads();

    unsigned long long acc[NNODE][2];
#pragma unroll
    for(int n=0;n<NNODE;n++){ acc[n][0]=0ull; acc[n][1]=0ull; }

    const float4* whp = (const float4*)Wh + tid;
#pragma unroll
    for(int m=0;m<NNODE;m++){
        float4 w = whp[m*(FF/4)];
        unsigned long long w01 = pk2(w.x,w.y);
        unsigned long long w23 = pk2(w.z,w.w);
#pragma unroll
        for(int n=0;n<NNODE;n++){
            float at = satt[n][m];
            unsigned long long ap = pk2(at,at);
            fma2(acc[n][0], ap, w01);
            fma2(acc[n][1], ap, w23);
        }
    }
    float* out = g_hp + (size_t)hb * NF + tid*4;
#pragma unroll
    for(int n=0;n<NNODE;n++){
        float2 a0 = upk(acc[n][0]);
        float2 a1 = upk(acc[n][1]);
        *(float4*)(out + (size_t)n*FF) = make_float4(a0.x,a0.y,a1.x,a1.y);
    }
}

// ============================================================================
// K3: split-K tf32 GEMM: part[h*8+kc][b][o] = sum_{f in 1792-chunk} hp[h,b,f]*fcw[h,o,f]
// Block = (h, ot in 4 of 256 o's, kc in 8). M=32(b) -> 2 m16-tiles; N=256;
// 8 warps x 32 n-cols. A (hp) hi/lo split in regs; B (fcw) raw tf32.
// ============================================================================
#define K3_AP 20
#define K3_BP 20
__global__ __launch_bounds__(256) void k3_fc(const float* __restrict__ fcw){
    __shared__ float sA[2][32][K3_AP];
    __shared__ float sB[2][256][K3_BP];

    const int blk = blockIdx.x;             // h*32 + ot*8 + kc
    const int h   = blk >> 5;
    const int ot  = (blk >> 3) & 3;
    const int kc  = blk & 7;
    const int f0  = kc * 1792;
    const int tid = threadIdx.x;
    const int lane = tid & 31;
    const int w    = tid >> 5;

    const float* hpB = g_hp + (size_t)h * BB * NF;
    const float* wB  = fcw  + (size_t)h * FF * NF + (size_t)(ot*256) * NF;

    float acc[2][4][4];
#pragma unroll
    for(int mt=0;mt<2;mt++)
#pragma unroll
    for(int j=0;j<4;j++){ acc[mt][j][0]=0.f; acc[mt][j][1]=0.f; acc[mt][j][2]=0.f; acc[mt][j][3]=0.f; }

    // prefetch chunk 0
    {
#pragma unroll
        for(int j=0;j<4;j++){
            int idx = tid + j*256;           // 1024 float4 (256 o x 4)
            int o   = idx >> 2;
            int f4  = (idx & 3) << 2;
            cpasync16(su32(&sB[0][o][f4]), wB + (size_t)o*NF + f0 + f4);
        }
        if(tid < 128){
            int bq = tid >> 2;
            int f4 = (tid & 3) << 2;
            cpasync16(su32(&sA[0][bq][f4]), hpB + (size_t)bq*NF + f0 + f4);
        }
        cpcommit();
    }

    const int ak = lane & 3;
    const int ar = lane >> 2;

    for(int c=0;c<112;c++){
        const int buf = c & 1;
        if(c < 111){
            const int fb = f0 + (c+1)*16;
#pragma unroll
            for(int j=0;j<4;j++){
                int idx = tid + j*256;
                int o   = idx >> 2;
                int f4  = (idx & 3) << 2;
                cpasync16(su32(&sB[buf^1][o][f4]), wB + (size_t)o*NF + fb + f4);
            }
            if(tid < 128){
                int bq = tid >> 2;
                int f4 = (tid & 3) << 2;
                cpasync16(su32(&sA[buf^1][bq][f4]), hpB + (size_t)bq*NF + fb + f4);
            }
            cpcommit();
            cpwait<1>();
        } else {
            cpwait<0>();
        }
        __syncthreads();

#pragma unroll
        for(int kh=0;kh<2;kh++){
            const int k0 = kh*8;
            unsigned hfr[2][4], lfr[2][4];
#pragma unroll
            for(int mt=0;mt<2;mt++){
                float a0f = sA[buf][mt*16 + ar    ][k0 + ak];
                float a1f = sA[buf][mt*16 + ar + 8][k0 + ak];
                float a2f = sA[buf][mt*16 + ar    ][k0 + ak + 4];
                float a3f = sA[buf][mt*16 + ar + 8][k0 + ak + 4];
                hfr[mt][0] = __float_as_uint(a0f) & TF32_MASK;
                hfr[mt][1] = __float_as_uint(a1f) & TF32_MASK;
                hfr[mt][2] = __float_as_uint(a2f) & TF32_MASK;
                hfr[mt][3] = __float_as_uint(a3f) & TF32_MASK;
                lfr[mt][0] = __float_as_uint(a0f - __uint_as_float(hfr[mt][0]));
                lfr[mt][1] = __float_as_uint(a1f - __uint_as_float(hfr[mt][1]));
                lfr[mt][2] = __float_as_uint(a2f - __uint_as_float(hfr[mt][2]));
                lfr[mt][3] = __float_as_uint(a3f - __uint_as_float(hfr[mt][3]));
            }
#pragma unroll
            for(int j=0;j<4;j++){
                int nb = w*32 + j*8 + (lane>>2);
                unsigned b0 = __float_as_uint(sB[buf][nb][k0 + ak]);
                unsigned b1 = __float_as_uint(sB[buf][nb][k0 + ak + 4]);
                mma_tf32(acc[0][j], hfr[0][0],hfr[0][1],hfr[0][2],hfr[0][3], b0,b1);
                mma_tf32(acc[0][j], lfr[0][0],lfr[0][1],lfr[0][2],lfr[0][3], b0,b1);
                mma_tf32(acc[1][j], hfr[1][0],hfr[1][1],hfr[1][2],hfr[1][3], b0,b1);
                mma_tf32(acc[1][j], lfr[1][0],lfr[1][1],lfr[1][2],lfr[1][3], b0,b1);
            }
        }
        __syncthreads();
    }

    const int kbi = h*8 + kc;
    float* pp = g_part + (size_t)kbi * BB * FF;
#pragma unroll
    for(int mt=0;mt<2;mt++)
#pragma unroll
    for(int j=0;j<4;j++){
        int col = ot*256 + w*32 + j*8 + 2*(lane&3);
        int r   = mt*16 + (lane>>2);
        *(float2*)(pp + (size_t)r*FF + col)     = make_float2(acc[mt][j][0], acc[mt][j][1]);
        *(float2*)(pp + (size_t)(r+8)*FF + col) = make_float2(acc[mt][j][2], acc[mt][j][3]);
    }
}

// ============================================================================
// K4a: g_red[b][o] = sum_kb part[kb][b][o] + sum_h fcb[h][o]    (128 blocks)
// ============================================================================
__global__ __launch_bounds__(256) void k4a(const float* __restrict__ fcb){
    const int blk = blockIdx.x;      // b*4 + ot
    const int b   = blk >> 2;
    const int o   = (blk & 3)*256 + threadIdx.x;
    float s = 0.f;
#pragma unroll 8
    for(int kb=0;kb<32;kb++)
        s += g_part[((size_t)kb*BB + b)*FF + o];
    float bias = 0.f;
#pragma unroll
    for(int h=0;h<HH;h++) bias += fcb[h*FF + o];
    g_red[b*FF + o] = s + bias;
}

// ============================================================================
// K4b: out[b,:] = log_softmax(g_red[b,:])    (32 blocks)
// ============================================================================
__global__ __launch_bounds__(256) void k4b(float* __restrict__ out){
    const int b   = blockIdx.x;
    const int tid = threadIdx.x;
    const int wid = tid>>5, lid = tid&31;

    __shared__ float smax[8];
    __shared__ float ssum[8];

    float v[4];
#pragma unroll
    for(int j=0;j<4;j++) v[j] = g_red[b*FF + tid + j*256];

    float mx = fmaxf(fmaxf(v[0],v[1]), fmaxf(v[2],v[3]));
#pragma unroll
    for(int off=16;off;off>>=1) mx = fmaxf(mx, __shfl_xor_sync(0xFFFFFFFFu, mx, off));
    if(lid==0) smax[wid]=mx;
    __syncthreads();
    if(tid==0){
        float m = smax[0];
#pragma unroll
        for(int i=1;i<8;i++) m = fmaxf(m, smax[i]);
        smax[0]=m;
    }
    __syncthreads();
    float bm = smax[0];

    float s = 0.f;
#pragma unroll
    for(int j=0;j<4;j++) s += expf(v[j]-bm);
#pragma unroll
    for(int off=16;off;off>>=1) s += __shfl_xor_sync(0xFFFFFFFFu, s, off);
    if(lid==0) ssum[wid]=s;
    __syncthreads();
    if(tid==0){
        float t=0.f;
#pragma unroll
        for(int i=0;i<8;i++) t += ssum[i];
        ssum[0]=t;
    }
    __syncthreads();
    float lse = bm + logf(ssum[0]);

#pragma unroll
    for(int j=0;j<4;j++)
        out[(size_t)b*FF + tid + j*256] = v[j] - lse;
}

// ============================================================================
extern "C" void kernel_launch(void* const* d_in, const int* in_sizes, int n_in,
                              void* d_out, int out_size){
    const float* x   = (const float*)d_in[0];
    const float* adj = (const float*)d_in[1];
    const float* W   = (const float*)d_in[2];
    const float* a   = (const float*)d_in[3];
    const float* fcw = (const float*)d_in[4];
    const float* fcb = (const float*)d_in[5];
    float* out = (float*)d_out;

    cudaFuncSetAttribute(k1_wh, cudaFuncAttributeMaxDynamicSharedMemorySize, K1_SMEM);

    k1_wh <<<HH*BB, 256, K1_SMEM>>>(x, W);
    k2_att<<<HH*BB, 256>>>(adj, a);
    k3_fc <<<128, 256>>>(fcw);
    k4a   <<<BB*4, 256>>>(fcb);
    k4b   <<<BB, 256>>>(out);
}

// round 6
// speedup vs baseline: 2.5718x; 1.1200x over previous
#include <cuda_runtime.h>

#define HH 4
#define BB 32
#define NNODE 14
#define FF 1024
#define NF (NNODE*FF)   // 14336
#define KSPLIT 64       // k3 partial slices (h*16 + kc)

#define ALPHA_SLOPE 0.2f
#define NEGV (-9000000000000000.0f)

// Scratch (no allocation allowed)
static __device__ float g_hp[HH*BB*NNODE*FF];   // 7 MB
static __device__ float g_part[KSPLIT*BB*FF];   // 8 MB

// ---- packed fp32x2 helpers ----
__device__ __forceinline__ unsigned long long pk2(float a, float b){
    unsigned long long r;
    asm("mov.b64 %0, {%1, %2};" : "=l"(r) : "f"(a), "f"(b));
    return r;
}
__device__ __forceinline__ void fma2(unsigned long long &d, unsigned long long a, unsigned long long b){
    asm("fma.rn.f32x2 %0, %1, %2, %0;" : "+l"(d) : "l"(a), "l"(b));
}
__device__ __forceinline__ float2 upk(unsigned long long v){
    float2 r;
    asm("mov.b64 {%0, %1}, %2;" : "=f"(r.x), "=f"(r.y) : "l"(v));
    return r;
}

// ---- cp.async helpers ----
__device__ __forceinline__ unsigned su32(const void* p){
    return (unsigned)__cvta_generic_to_shared(p);
}
__device__ __forceinline__ void cpasync16(unsigned dst, const void* src){
    asm volatile("cp.async.cg.shared.global [%0], [%1], 16;\n" :: "r"(dst), "l"(src));
}
__device__ __forceinline__ void cpcommit(){ asm volatile("cp.async.commit_group;\n" ::: "memory"); }
template<int N> __device__ __forceinline__ void cpwait(){
    asm volatile("cp.async.wait_group %0;\n" :: "n"(N) : "memory");
}

// ---- tf32 mma.sync (m16n8k8), D += A*B, fp32 accum ----
__device__ __forceinline__ void mma_tf32(float* d,
    unsigned a0, unsigned a1, unsigned a2, unsigned a3,
    unsigned b0, unsigned b1){
    asm volatile("mma.sync.aligned.m16n8k8.row.col.f32.tf32.tf32.f32 "
        "{%0,%1,%2,%3}, {%4,%5,%6,%7}, {%8,%9}, {%0,%1,%2,%3};\n"
        : "+f"(d[0]), "+f"(d[1]), "+f"(d[2]), "+f"(d[3])
        : "r"(a0), "r"(a1), "r"(a2), "r"(a3), "r"(b0), "r"(b1));
}

#define TF32_MASK 0xFFFFE000u   // keep sign+exp+top10 mantissa

// ============================================================================
// K1 (fused with attention): per block (h,b):
//   Wh (16x1024, rows>=14 zero) = x[b] * W[h,b]   [tf32 MMA, A hi/lo split]
//   then in-block: s1,s2 reductions; 14x14 masked softmax; h_prime = att*Wh
//   writes g_hp only. 8 warps x 128 N-cols, K chunk 16, cp.async dbl-buffer.
// ============================================================================
#define K1_PITCH 1032
#define K1_SMEM ((16*K1_PITCH + 2*16*K1_PITCH)*4)

__global__ __launch_bounds__(256) void k1_wh(const float* __restrict__ x,
                                             const float* __restrict__ W,
                                             const float* __restrict__ adj,
                                             const float* __restrict__ attv){
    extern __shared__ float smem[];
    float* sA = smem;                       // [16][1032]
    float* sB = smem + 16*K1_PITCH;         // [2][16][1032]

    __shared__ float s_s1[NNODE], s_s2[NNODE];
    __shared__ float satt[NNODE][NNODE];
    __shared__ float red[2*NNODE][8];

    const int hb   = blockIdx.x;
    const int b    = hb & (BB-1);
    const int tid  = threadIdx.x;
    const int lane = tid & 31;
    const int w    = tid >> 5;

    const float* xb = x + (size_t)b * NNODE * FF;
    const float* Wp = W + (size_t)hb * FF * FF;

    float acc[16][4];
#pragma unroll
    for(int j=0;j<16;j++){ acc[j][0]=0.f; acc[j][1]=0.f; acc[j][2]=0.f; acc[j][3]=0.f; }

    // prefetch B chunk 0
    {
#pragma unroll
        for(int j=0;j<16;j++){
            int idx = tid + j*256;
            int r   = idx >> 8;
            int n4  = (idx & 255) << 2;
            cpasync16(su32(&sB[r*K1_PITCH + n4]), Wp + r*FF + n4);
        }
        cpcommit();
    }

    // stage A (x), zero-padded to 16 rows
#pragma unroll
    for(int j=0;j<16;j++){
        int idx = tid + j*256;
        int r   = idx >> 8;
        int k4  = (idx & 255) << 2;
        float4 v = make_float4(0.f,0.f,0.f,0.f);
        if(r < NNODE) v = *(const float4*)(xb + r*FF + k4);
        *(float4*)(&sA[r*K1_PITCH + k4]) = v;
    }

    const int ar = lane >> 2;
    const int ak = lane & 3;

    for(int c=0;c<64;c++){
        const int buf = c & 1;
        if(c < 63){
            const float* src = Wp + (size_t)(c+1)*16*FF;
#pragma unroll
            for(int j=0;j<16;j++){
                int idx = tid + j*256;
                int r   = idx >> 8;
                int n4  = (idx & 255) << 2;
                cpasync16(su32(&sB[((buf^1)*16 + r)*K1_PITCH + n4]), src + r*FF + n4);
            }
            cpcommit();
            cpwait<1>();
        } else {
            cpwait<0>();
        }
        __syncthreads();

        const float* Bb = &sB[buf*16*K1_PITCH];
#pragma unroll
        for(int kh=0;kh<2;kh++){
            const int k0 = kh*8;
            const int ac = c*16 + k0 + ak;
            float a0f = sA[ar*K1_PITCH + ac];
            float a1f = sA[(ar+8)*K1_PITCH + ac];
            float a2f = sA[ar*K1_PITCH + ac + 4];
            float a3f = sA[(ar+8)*K1_PITCH + ac + 4];
            unsigned h0 = __float_as_uint(a0f) & TF32_MASK;
            unsigned h1 = __float_as_uint(a1f) & TF32_MASK;
            unsigned h2 = __float_as_uint(a2f) & TF32_MASK;
            unsigned h3 = __float_as_uint(a3f) & TF32_MASK;
            unsigned l0 = __float_as_uint(a0f - __uint_as_float(h0));
            unsigned l1 = __float_as_uint(a1f - __uint_as_float(h1));
            unsigned l2 = __float_as_uint(a2f - __uint_as_float(h2));
            unsigned l3 = __float_as_uint(a3f - __uint_as_float(h3));
#pragma unroll
            for(int j=0;j<16;j++){
                int nb = w*128 + j*8 + (lane>>2);
                unsigned b0 = __float_as_uint(Bb[(k0 + ak)*K1_PITCH + nb]);
                unsigned b1 = __float_as_uint(Bb[(k0 + ak + 4)*K1_PITCH + nb]);
                mma_tf32(acc[j], h0,h1,h2,h3, b0,b1);
                mma_tf32(acc[j], l0,l1,l2,l3, b0,b1);
            }
        }
        __syncthreads();
    }

    // ---- fused attention epilogue ----
    // stage full Wh tile (16 rows, rows>=14 are exactly 0) into sB region
    float* sWh = sB;   // [16][1032]
    {
        const int r0 = lane >> 2;
#pragma unroll
        for(int j=0;j<16;j++){
            int col = w*128 + j*8 + 2*(lane&3);
            sWh[r0*K1_PITCH + col]     = acc[j][0];
            sWh[r0*K1_PITCH + col + 1] = acc[j][1];
            sWh[(r0+8)*K1_PITCH + col]     = acc[j][2];
            sWh[(r0+8)*K1_PITCH + col + 1] = acc[j][3];
        }
    }
    __syncthreads();

    // s1[n] = Wh[n,:]·a1, s2[n] = Wh[n,:]·a2 ; thread owns 4 cols c0..c0+3
    const int c0 = tid * 4;
    const float* av = attv + (size_t)hb * 2 * FF;
    {
        float4 a1v = *(const float4*)(av + c0);
        float4 a2v = *(const float4*)(av + FF + c0);
        float p1[NNODE], p2[NNODE];
#pragma unroll
        for(int n=0;n<NNODE;n++){
            float4 wv = *(const float4*)(&sWh[n*K1_PITCH + c0]);
            p1[n] = wv.x*a1v.x + wv.y*a1v.y + wv.z*a1v.z + wv.w*a1v.w;
            p2[n] = wv.x*a2v.x + wv.y*a2v.y + wv.z*a2v.z + wv.w*a2v.w;
        }
#pragma unroll
        for(int n=0;n<NNODE;n++){
#pragma unroll
            for(int off=16;off;off>>=1){
                p1[n] += __shfl_xor_sync(0xFFFFFFFFu, p1[n], off);
                p2[n] += __shfl_xor_sync(0xFFFFFFFFu, p2[n], off);
            }
        }
        if(lane==0){
#pragma unroll
            for(int n=0;n<NNODE;n++){ red[n][w]=p1[n]; red[NNODE+n][w]=p2[n]; }
        }
    }
    __syncthreads();
    if(tid < 2*NNODE){
        float s=0.f;
#pragma unroll
        for(int q=0;q<8;q++) s += red[tid][q];
        if(tid < NNODE) s_s1[tid] = s; else s_s2[tid-NNODE] = s;
    }
    __syncthreads();

    // masked softmax over n (per column m)
    if(tid < NNODE){
        int m = tid;
        float col[NNODE];
        float mx = -3.4e38f;
#pragma unroll
        for(int n=0;n<NNODE;n++){
            float e = s_s1[n] + s_s2[m];
            e = (e > 0.f) ? e : ALPHA_SLOPE*e;
            float v = (adj[(size_t)b*NNODE*NNODE + n*NNODE + m] > 0.f) ? e : NEGV;
            col[n] = v;
            mx = fmaxf(mx, v);
        }
        float sum = 0.f;
#pragma unroll
        for(int n=0;n<NNODE;n++){
            col[n] = expf(col[n]-mx);
            sum += col[n];
        }
        float inv = 1.f/sum;
#pragma unroll
        for(int n=0;n<NNODE;n++) satt[n][m] = col[n]*inv;
    }
    __syncthreads();

    // h_prime[n, c0..c0+3] = sum_m satt[n][m] * Wh[m, c0..c0+3]
    {
        unsigned long long hp01[NNODE], hp23[NNODE];
#pragma unroll
        for(int n=0;n<NNODE;n++){ hp01[n]=0ull; hp23[n]=0ull; }
#pragma unroll
        for(int m=0;m<NNODE;m++){
            float4 wv = *(const float4*)(&sWh[m*K1_PITCH + c0]);
            unsigned long long w01 = pk2(wv.x,wv.y);
            unsigned long long w23 = pk2(wv.z,wv.w);
#pragma unroll
            for(int n=0;n<NNODE;n++){
                float at = satt[n][m];
                unsigned long long ap = pk2(at,at);
                fma2(hp01[n], ap, w01);
                fma2(hp23[n], ap, w23);
            }
        }
        float* outp = g_hp + (size_t)hb * NF + c0;
#pragma unroll
        for(int n=0;n<NNODE;n++){
            float2 q0 = upk(hp01[n]);
            float2 q1 = upk(hp23[n]);
            *(float4*)(outp + (size_t)n*FF) = make_float4(q0.x,q0.y,q1.x,q1.y);
        }
    }
}

// ============================================================================
// K3: split-K tf32 GEMM: part[h*16+kc][b][o] = sum_{f in 896-chunk} hp[h,b,f]*fcw[h,o,f]
// Grid 256 = h(4) x ot(4, 256 o's) x kc(16). 56 K-chunks of 16 per block.
// A (hp) hi/lo split; B (fcw) raw tf32. ~2 CTAs/SM hides pipeline bubbles.
// ============================================================================
#define K3_AP 20
#define K3_BP 20
__global__ __launch_bounds__(256) void k3_fc(const float* __restrict__ fcw){
    __shared__ float sA[2][32][K3_AP];
    __shared__ float sB[2][256][K3_BP];

    const int blk = blockIdx.x;             // h*64 + ot*16 + kc
    const int h   = blk >> 6;
    const int ot  = (blk >> 4) & 3;
    const int kc  = blk & 15;
    const int f0  = kc * 896;
    const int tid = threadIdx.x;
    const int lane = tid & 31;
    const int w    = tid >> 5;

    const float* hpB = g_hp + (size_t)h * BB * NF;
    const float* wB  = fcw  + (size_t)h * FF * NF + (size_t)(ot*256) * NF;

    float acc[2][4][4];
#pragma unroll
    for(int mt=0;mt<2;mt++)
#pragma unroll
    for(int j=0;j<4;j++){ acc[mt][j][0]=0.f; acc[mt][j][1]=0.f; acc[mt][j][2]=0.f; acc[mt][j][3]=0.f; }

    // prefetch chunk 0
    {
#pragma unroll
        for(int j=0;j<4;j++){
            int idx = tid + j*256;
            int o   = idx >> 2;
            int f4  = (idx & 3) << 2;
            cpasync16(su32(&sB[0][o][f4]), wB + (size_t)o*NF + f0 + f4);
        }
        if(tid < 128){
            int bq = tid >> 2;
            int f4 = (tid & 3) << 2;
            cpasync16(su32(&sA[0][bq][f4]), hpB + (size_t)bq*NF + f0 + f4);
        }
        cpcommit();
    }

    const int ak = lane & 3;
    const int ar = lane >> 2;

    for(int c=0;c<56;c++){
        const int buf = c & 1;
        if(c < 55){
            const int fb = f0 + (c+1)*16;
#pragma unroll
            for(int j=0;j<4;j++){
                int idx = tid + j*256;
                int o   = idx >> 2;
                int f4  = (idx & 3) << 2;
                cpasync16(su32(&sB[buf^1][o][f4]), wB + (size_t)o*NF + fb + f4);
            }
            if(tid < 128){
                int bq = tid >> 2;
                int f4 = (tid & 3) << 2;
                cpasync16(su32(&sA[buf^1][bq][f4]), hpB + (size_t)bq*NF + fb + f4);
            }
            cpcommit();
            cpwait<1>();
        } else {
            cpwait<0>();
        }
        __syncthreads();

#pragma unroll
        for(int kh=0;kh<2;kh++){
            const int k0 = kh*8;
            unsigned hfr[2][4], lfr[2][4];
#pragma unroll
            for(int mt=0;mt<2;mt++){
                float a0f = sA[buf][mt*16 + ar    ][k0 + ak];
                float a1f = sA[buf][mt*16 + ar + 8][k0 + ak];
                float a2f = sA[buf][mt*16 + ar    ][k0 + ak + 4];
                float a3f = sA[buf][mt*16 + ar + 8][k0 + ak + 4];
                hfr[mt][0] = __float_as_uint(a0f) & TF32_MASK;
                hfr[mt][1] = __float_as_uint(a1f) & TF32_MASK;
                hfr[mt][2] = __float_as_uint(a2f) & TF32_MASK;
                hfr[mt][3] = __float_as_uint(a3f) & TF32_MASK;
                lfr[mt][0] = __float_as_uint(a0f - __uint_as_float(hfr[mt][0]));
                lfr[mt][1] = __float_as_uint(a1f - __uint_as_float(hfr[mt][1]));
                lfr[mt][2] = __float_as_uint(a2f - __uint_as_float(hfr[mt][2]));
                lfr[mt][3] = __float_as_uint(a3f - __uint_as_float(hfr[mt][3]));
            }
#pragma unroll
            for(int j=0;j<4;j++){
                int nb = w*32 + j*8 + (lane>>2);
                unsigned b0 = __float_as_uint(sB[buf][nb][k0 + ak]);
                unsigned b1 = __float_as_uint(sB[buf][nb][k0 + ak + 4]);
                mma_tf32(acc[0][j], hfr[0][0],hfr[0][1],hfr[0][2],hfr[0][3], b0,b1);
                mma_tf32(acc[0][j], lfr[0][0],lfr[0][1],lfr[0][2],lfr[0][3], b0,b1);
                mma_tf32(acc[1][j], hfr[1][0],hfr[1][1],hfr[1][2],hfr[1][3], b0,b1);
                mma_tf32(acc[1][j], lfr[1][0],lfr[1][1],lfr[1][2],lfr[1][3], b0,b1);
            }
        }
        __syncthreads();
    }

    const int kbi = h*16 + kc;
    float* pp = g_part + (size_t)kbi * BB * FF;
#pragma unroll
    for(int mt=0;mt<2;mt++)
#pragma unroll
    for(int j=0;j<4;j++){
        int col = ot*256 + w*32 + j*8 + 2*(lane&3);
        int r   = mt*16 + (lane>>2);
        *(float2*)(pp + (size_t)r*FF + col)     = make_float2(acc[mt][j][0], acc[mt][j][1]);
        *(float2*)(pp + (size_t)(r+8)*FF + col) = make_float2(acc[mt][j][2], acc[mt][j][3]);
    }
}

// ============================================================================
// K4 (fused): out[b,:] = log_softmax( sum_kb part[kb][b][:] + sum_h fcb[h][:] )
// 32 blocks x 1024 threads (1 o per thread).
// ============================================================================
__global__ __launch_bounds__(1024) void k4_out(const float* __restrict__ fcb,
                                               float* __restrict__ out){
    const int b   = blockIdx.x;
    const int o   = threadIdx.x;
    const int wid = o >> 5, lid = o & 31;

    __shared__ float sred[32];

    float s = 0.f;
#pragma unroll 8
    for(int kb=0;kb<KSPLIT;kb++)
        s += g_part[((size_t)kb*BB + b)*FF + o];
    float bias = 0.f;
#pragma unroll
    for(int h=0;h<HH;h++) bias += fcb[h*FF + o];
    float v = s + bias;

    // block max
    float mx = v;
#pragma unroll
    for(int off=16;off;off>>=1) mx = fmaxf(mx, __shfl_xor_sync(0xFFFFFFFFu, mx, off));
    if(lid==0) sred[wid]=mx;
    __syncthreads();
    if(wid==0){
        float m = sred[lid];
#pragma unroll
        for(int off=16;off;off>>=1) m = fmaxf(m, __shfl_xor_sync(0xFFFFFFFFu, m, off));
        if(lid==0) sred[0]=m;
    }
    __syncthreads();
    float bm = sred[0];
    __syncthreads();

    // block sum of exp
    float e = expf(v-bm);
    float sm = e;
#pragma unroll
    for(int off=16;off;off>>=1) sm += __shfl_xor_sync(0xFFFFFFFFu, sm, off);
    if(lid==0) sred[wid]=sm;
    __syncthreads();
    if(wid==0){
        float t = sred[lid];
#pragma unroll
        for(int off=16;off;off>>=1) t += __shfl_xor_sync(0xFFFFFFFFu, t, off);
        if(lid==0) sred[0]=t;
    }
    __syncthreads();
    float lse = bm + logf(sred[0]);

    out[(size_t)b*FF + o] = v - lse;
}

// ============================================================================
extern "C" void kernel_launch(void* const* d_in, const int* in_sizes, int n_in,
                              void* d_out, int out_size){
    const float* x   = (const float*)d_in[0];
    const float* adj = (const float*)d_in[1];
    const float* W   = (const float*)d_in[2];
    const float* a   = (const float*)d_in[3];
    const float* fcw = (const float*)d_in[4];
    const float* fcb = (const float*)d_in[5];
    float* out = (float*)d_out;

    cudaFuncSetAttribute(k1_wh, cudaFuncAttributeMaxDynamicSharedMemorySize, K1_SMEM);

    k1_wh <<<HH*BB, 256, K1_SMEM>>>(x, W, adj, a);
    k3_fc <<<256, 256>>>(fcw);
    k4_out<<<BB, 1024>>>(fcb, out);
}

// round 7
// speedup vs baseline: 2.7568x; 1.0719x over previous
#include <cuda_runtime.h>

#define HH 4
#define BB 32
#define NNODE 14
#define FF 1024
#define NF (NNODE*FF)   // 14336
#define KSPLIT 64       // k3 partial slices (h*16 + kc)

#define ALPHA_SLOPE 0.2f
#define NEGV (-9000000000000000.0f)

// Scratch (no allocation allowed)
static __device__ float g_hp[HH*BB*NNODE*FF];   // 7 MB
static __device__ float g_part[KSPLIT*BB*FF];   // 8 MB

// ---- packed fp32x2 helpers ----
__device__ __forceinline__ unsigned long long pk2(float a, float b){
    unsigned long long r;
    asm("mov.b64 %0, {%1, %2};" : "=l"(r) : "f"(a), "f"(b));
    return r;
}
__device__ __forceinline__ void fma2(unsigned long long &d, unsigned long long a, unsigned long long b){
    asm("fma.rn.f32x2 %0, %1, %2, %0;" : "+l"(d) : "l"(a), "l"(b));
}
__device__ __forceinline__ float2 upk(unsigned long long v){
    float2 r;
    asm("mov.b64 {%0, %1}, %2;" : "=f"(r.x), "=f"(r.y) : "l"(v));
    return r;
}

// ---- cp.async helpers ----
__device__ __forceinline__ unsigned su32(const void* p){
    return (unsigned)__cvta_generic_to_shared(p);
}
__device__ __forceinline__ void cpasync16(unsigned dst, const void* src){
    asm volatile("cp.async.cg.shared.global [%0], [%1], 16;\n" :: "r"(dst), "l"(src));
}
__device__ __forceinline__ void cpcommit(){ asm volatile("cp.async.commit_group;\n" ::: "memory"); }
template<int N> __device__ __forceinline__ void cpwait(){
    asm volatile("cp.async.wait_group %0;\n" :: "n"(N) : "memory");
}

// ---- tf32 mma.sync (m16n8k8), D += A*B, fp32 accum ----
__device__ __forceinline__ void mma_tf32(float* d,
    unsigned a0, unsigned a1, unsigned a2, unsigned a3,
    unsigned b0, unsigned b1){
    asm volatile("mma.sync.aligned.m16n8k8.row.col.f32.tf32.tf32.f32 "
        "{%0,%1,%2,%3}, {%4,%5,%6,%7}, {%8,%9}, {%0,%1,%2,%3};\n"
        : "+f"(d[0]), "+f"(d[1]), "+f"(d[2]), "+f"(d[3])
        : "r"(a0), "r"(a1), "r"(a2), "r"(a3), "r"(b0), "r"(b1));
}

#define TF32_MASK 0xFFFFE000u   // keep sign+exp+top10 mantissa

// ============================================================================
// K1 (fused with attention): per block (h,b):
//   Wh (16x1024, rows>=14 zero) = x[b] * W[h,b]   [tf32 MMA, A hi/lo split]
//   then in-block: s1,s2 reductions; 14x14 masked softmax; h_prime = att*Wh
//   writes g_hp only. 8 warps x 128 N-cols, K chunk 16, cp.async dbl-buffer.
//   (Profiled at DRAM 78% / 6.2 TB/s — at roofline; unchanged.)
// ============================================================================
#define K1_PITCH 1032
#define K1_SMEM ((16*K1_PITCH + 2*16*K1_PITCH)*4)

__global__ __launch_bounds__(256) void k1_wh(const float* __restrict__ x,
                                             const float* __restrict__ W,
                                             const float* __restrict__ adj,
                                             const float* __restrict__ attv){
    extern __shared__ float smem[];
    float* sA = smem;                       // [16][1032]
    float* sB = smem + 16*K1_PITCH;         // [2][16][1032]

    __shared__ float s_s1[NNODE], s_s2[NNODE];
    __shared__ float satt[NNODE][NNODE];
    __shared__ float red[2*NNODE][8];

    const int hb   = blockIdx.x;
    const int b    = hb & (BB-1);
    const int tid  = threadIdx.x;
    const int lane = tid & 31;
    const int w    = tid >> 5;

    const float* xb = x + (size_t)b * NNODE * FF;
    const float* Wp = W + (size_t)hb * FF * FF;

    float acc[16][4];
#pragma unroll
    for(int j=0;j<16;j++){ acc[j][0]=0.f; acc[j][1]=0.f; acc[j][2]=0.f; acc[j][3]=0.f; }

    // prefetch B chunk 0
    {
#pragma unroll
        for(int j=0;j<16;j++){
            int idx = tid + j*256;
            int r   = idx >> 8;
            int n4  = (idx & 255) << 2;
            cpasync16(su32(&sB[r*K1_PITCH + n4]), Wp + r*FF + n4);
        }
        cpcommit();
    }

    // stage A (x), zero-padded to 16 rows
#pragma unroll
    for(int j=0;j<16;j++){
        int idx = tid + j*256;
        int r   = idx >> 8;
        int k4  = (idx & 255) << 2;
        float4 v = make_float4(0.f,0.f,0.f,0.f);
        if(r < NNODE) v = *(const float4*)(xb + r*FF + k4);
        *(float4*)(&sA[r*K1_PITCH + k4]) = v;
    }

    const int ar = lane >> 2;
    const int ak = lane & 3;

    for(int c=0;c<64;c++){
        const int buf = c & 1;
        if(c < 63){
            const float* src = Wp + (size_t)(c+1)*16*FF;
#pragma unroll
            for(int j=0;j<16;j++){
                int idx = tid + j*256;
                int r   = idx >> 8;
                int n4  = (idx & 255) << 2;
                cpasync16(su32(&sB[((buf^1)*16 + r)*K1_PITCH + n4]), src + r*FF + n4);
            }
            cpcommit();
            cpwait<1>();
        } else {
            cpwait<0>();
        }
        __syncthreads();

        const float* Bb = &sB[buf*16*K1_PITCH];
#pragma unroll
        for(int kh=0;kh<2;kh++){
            const int k0 = kh*8;
            const int ac = c*16 + k0 + ak;
            float a0f = sA[ar*K1_PITCH + ac];
            float a1f = sA[(ar+8)*K1_PITCH + ac];
            float a2f = sA[ar*K1_PITCH + ac + 4];
            float a3f = sA[(ar+8)*K1_PITCH + ac + 4];
            unsigned h0 = __float_as_uint(a0f) & TF32_MASK;
            unsigned h1 = __float_as_uint(a1f) & TF32_MASK;
            unsigned h2 = __float_as_uint(a2f) & TF32_MASK;
            unsigned h3 = __float_as_uint(a3f) & TF32_MASK;
            unsigned l0 = __float_as_uint(a0f - __uint_as_float(h0));
            unsigned l1 = __float_as_uint(a1f - __uint_as_float(h1));
            unsigned l2 = __float_as_uint(a2f - __uint_as_float(h2));
            unsigned l3 = __float_as_uint(a3f - __uint_as_float(h3));
#pragma unroll
            for(int j=0;j<16;j++){
                int nb = w*128 + j*8 + (lane>>2);
                unsigned b0 = __float_as_uint(Bb[(k0 + ak)*K1_PITCH + nb]);
                unsigned b1 = __float_as_uint(Bb[(k0 + ak + 4)*K1_PITCH + nb]);
                mma_tf32(acc[j], h0,h1,h2,h3, b0,b1);
                mma_tf32(acc[j], l0,l1,l2,l3, b0,b1);
            }
        }
        __syncthreads();
    }

    // ---- fused attention epilogue ----
    float* sWh = sB;   // [16][1032]
    {
        const int r0 = lane >> 2;
#pragma unroll
        for(int j=0;j<16;j++){
            int col = w*128 + j*8 + 2*(lane&3);
            sWh[r0*K1_PITCH + col]     = acc[j][0];
            sWh[r0*K1_PITCH + col + 1] = acc[j][1];
            sWh[(r0+8)*K1_PITCH + col]     = acc[j][2];
            sWh[(r0+8)*K1_PITCH + col + 1] = acc[j][3];
        }
    }
    __syncthreads();

    const int c0 = tid * 4;
    const float* av = attv + (size_t)hb * 2 * FF;
    {
        float4 a1v = *(const float4*)(av + c0);
        float4 a2v = *(const float4*)(av + FF + c0);
        float p1[NNODE], p2[NNODE];
#pragma unroll
        for(int n=0;n<NNODE;n++){
            float4 wv = *(const float4*)(&sWh[n*K1_PITCH + c0]);
            p1[n] = wv.x*a1v.x + wv.y*a1v.y + wv.z*a1v.z + wv.w*a1v.w;
            p2[n] = wv.x*a2v.x + wv.y*a2v.y + wv.z*a2v.z + wv.w*a2v.w;
        }
#pragma unroll
        for(int n=0;n<NNODE;n++){
#pragma unroll
            for(int off=16;off;off>>=1){
                p1[n] += __shfl_xor_sync(0xFFFFFFFFu, p1[n], off);
                p2[n] += __shfl_xor_sync(0xFFFFFFFFu, p2[n], off);
            }
        }
        if(lane==0){
#pragma unroll
            for(int n=0;n<NNODE;n++){ red[n][w]=p1[n]; red[NNODE+n][w]=p2[n]; }
        }
    }
    __syncthreads();
    if(tid < 2*NNODE){
        float s=0.f;
#pragma unroll
        for(int q=0;q<8;q++) s += red[tid][q];
        if(tid < NNODE) s_s1[tid] = s; else s_s2[tid-NNODE] = s;
    }
    __syncthreads();

    if(tid < NNODE){
        int m = tid;
        float col[NNODE];
        float mx = -3.4e38f;
#pragma unroll
        for(int n=0;n<NNODE;n++){
            float e = s_s1[n] + s_s2[m];
            e = (e > 0.f) ? e : ALPHA_SLOPE*e;
            float v = (adj[(size_t)b*NNODE*NNODE + n*NNODE + m] > 0.f) ? e : NEGV;
            col[n] = v;
            mx = fmaxf(mx, v);
        }
        float sum = 0.f;
#pragma unroll
        for(int n=0;n<NNODE;n++){
            col[n] = expf(col[n]-mx);
            sum += col[n];
        }
        float inv = 1.f/sum;
#pragma unroll
        for(int n=0;n<NNODE;n++) satt[n][m] = col[n]*inv;
    }
    __syncthreads();

    {
        unsigned long long hp01[NNODE], hp23[NNODE];
#pragma unroll
        for(int n=0;n<NNODE;n++){ hp01[n]=0ull; hp23[n]=0ull; }
#pragma unroll
        for(int m=0;m<NNODE;m++){
            float4 wv = *(const float4*)(&sWh[m*K1_PITCH + c0]);
            unsigned long long w01 = pk2(wv.x,wv.y);
            unsigned long long w23 = pk2(wv.z,wv.w);
#pragma unroll
            for(int n=0;n<NNODE;n++){
                float at = satt[n][m];
                unsigned long long ap = pk2(at,at);
                fma2(hp01[n], ap, w01);
                fma2(hp23[n], ap, w23);
            }
        }
        float* outp = g_hp + (size_t)hb * NF + c0;
#pragma unroll
        for(int n=0;n<NNODE;n++){
            float2 q0 = upk(hp01[n]);
            float2 q1 = upk(hp23[n]);
            *(float4*)(outp + (size_t)n*FF) = make_float4(q0.x,q0.y,q1.x,q1.y);
        }
    }
}

// ============================================================================
// K3: split-K tf32 GEMM: part[h*16+kc][b][o] = sum_{f in 896-chunk} hp[h,b,f]*fcw[h,o,f]
// Grid 256 = h(4) x ot(4, 256 o's) x kc(16). 56 K-chunks of 16 per block.
// DEPTH-4 cp.async pipeline (3 chunks in flight), ONE __syncthreads per iter.
// Dynamic smem 92 KB -> 2 CTAs/SM (launch_bounds(256,2) caps regs at 128).
// ============================================================================
#define K3_PITCH 20
#define K3_SMEM ((4*256*K3_PITCH + 4*32*K3_PITCH)*4)

__global__ __launch_bounds__(256,2) void k3_fc(const float* __restrict__ fcw){
    extern __shared__ float s3[];
    float* sB = s3;                          // [4][256][20]
    float* sA = s3 + 4*256*K3_PITCH;         // [4][32][20]

    const int blk = blockIdx.x;             // h*64 + ot*16 + kc
    const int h   = blk >> 6;
    const int ot  = (blk >> 4) & 3;
    const int kc  = blk & 15;
    const int f0  = kc * 896;
    const int tid = threadIdx.x;
    const int lane = tid & 31;
    const int w    = tid >> 5;

    const float* hpB = g_hp + (size_t)h * BB * NF;
    const float* wB  = fcw  + (size_t)h * FF * NF + (size_t)(ot*256) * NF;

    float acc[2][4][4];
#pragma unroll
    for(int mt=0;mt<2;mt++)
#pragma unroll
    for(int j=0;j<4;j++){ acc[mt][j][0]=0.f; acc[mt][j][1]=0.f; acc[mt][j][2]=0.f; acc[mt][j][3]=0.f; }

    auto issue = [&](int cc){
        const int s  = cc & 3;
        const int fb = f0 + cc*16;
#pragma unroll
        for(int j=0;j<4;j++){
            int idx = tid + j*256;           // 1024 float4 (256 o x 4)
            int o   = idx >> 2;
            int f4  = (idx & 3) << 2;
            cpasync16(su32(&sB[(s*256 + o)*K3_PITCH + f4]), wB + (size_t)o*NF + fb + f4);
        }
        if(tid < 128){
            int bq = tid >> 2;
            int f4 = (tid & 3) << 2;
            cpasync16(su32(&sA[(s*32 + bq)*K3_PITCH + f4]), hpB + (size_t)bq*NF + fb + f4);
        }
        cpcommit();
    };

    // prologue: 3 chunks in flight
    issue(0); issue(1); issue(2);

    const int ak = lane & 3;
    const int ar = lane >> 2;

    for(int c=0;c<56;c++){
        // wait for chunk c (issued chunks extend to min(55, c+2))
        if(c <= 53)      cpwait<2>();
        else if(c == 54) cpwait<1>();
        else             cpwait<0>();
        __syncthreads();          // data visible to all warps; all warps done with chunk c-1
        if(c + 3 < 56) issue(c + 3);   // overwrites stage (c-1)&3 — safe after sync

        const int s = c & 3;
        const float* sAs = &sA[s*32*K3_PITCH];
        const float* sBs = &sB[s*256*K3_PITCH];
#pragma unroll
        for(int kh=0;kh<2;kh++){
            const int k0 = kh*8;
            unsigned hfr[2][4], lfr[2][4];
#pragma unroll
            for(int mt=0;mt<2;mt++){
                float a0f = sAs[(mt*16 + ar    )*K3_PITCH + k0 + ak];
                float a1f = sAs[(mt*16 + ar + 8)*K3_PITCH + k0 + ak];
                float a2f = sAs[(mt*16 + ar    )*K3_PITCH + k0 + ak + 4];
                float a3f = sAs[(mt*16 + ar + 8)*K3_PITCH + k0 + ak + 4];
                hfr[mt][0] = __float_as_uint(a0f) & TF32_MASK;
                hfr[mt][1] = __float_as_uint(a1f) & TF32_MASK;
                hfr[mt][2] = __float_as_uint(a2f) & TF32_MASK;
                hfr[mt][3] = __float_as_uint(a3f) & TF32_MASK;
                lfr[mt][0] = __float_as_uint(a0f - __uint_as_float(hfr[mt][0]));
                lfr[mt][1] = __float_as_uint(a1f - __uint_as_float(hfr[mt][1]));
                lfr[mt][2] = __float_as_uint(a2f - __uint_as_float(hfr[mt][2]));
                lfr[mt][3] = __float_as_uint(a3f - __uint_as_float(hfr[mt][3]));
            }
#pragma unroll
            for(int j=0;j<4;j++){
                int nb = w*32 + j*8 + (lane>>2);
                unsigned b0 = __float_as_uint(sBs[nb*K3_PITCH + k0 + ak]);
                unsigned b1 = __float_as_uint(sBs[nb*K3_PITCH + k0 + ak + 4]);
                mma_tf32(acc[0][j], hfr[0][0],hfr[0][1],hfr[0][2],hfr[0][3], b0,b1);
                mma_tf32(acc[0][j], lfr[0][0],lfr[0][1],lfr[0][2],lfr[0][3], b0,b1);
                mma_tf32(acc[1][j], hfr[1][0],hfr[1][1],hfr[1][2],hfr[1][3], b0,b1);
                mma_tf32(acc[1][j], lfr[1][0],lfr[1][1],lfr[1][2],lfr[1][3], b0,b1);
            }
        }
    }

    const int kbi = h*16 + kc;
    float* pp = g_part + (size_t)kbi * BB * FF;
#pragma unroll
    for(int mt=0;mt<2;mt++)
#pragma unroll
    for(int j=0;j<4;j++){
        int col = ot*256 + w*32 + j*8 + 2*(lane&3);
        int r   = mt*16 + (lane>>2);
        *(float2*)(pp + (size_t)r*FF + col)     = make_float2(acc[mt][j][0], acc[mt][j][1]);
        *(float2*)(pp + (size_t)(r+8)*FF + col) = make_float2(acc[mt][j][2], acc[mt][j][3]);
    }
}

// ============================================================================
// K4 (fused): out[b,:] = log_softmax( sum_kb part[kb][b][:] + sum_h fcb[h][:] )
// 32 blocks x 1024 threads (1 o per thread).
// ============================================================================
__global__ __launch_bounds__(1024) void k4_out(const float* __restrict__ fcb,
                                               float* __restrict__ out){
    const int b   = blockIdx.x;
    const int o   = threadIdx.x;
    const int wid = o >> 5, lid = o & 31;

    __shared__ float sred[32];

    float s = 0.f;
#pragma unroll 8
    for(int kb=0;kb<KSPLIT;kb++)
        s += g_part[((size_t)kb*BB + b)*FF + o];
    float bias = 0.f;
#pragma unroll
    for(int h=0;h<HH;h++) bias += fcb[h*FF + o];
    float v = s + bias;

    float mx = v;
#pragma unroll
    for(int off=16;off;off>>=1) mx = fmaxf(mx, __shfl_xor_sync(0xFFFFFFFFu, mx, off));
    if(lid==0) sred[wid]=mx;
    __syncthreads();
    if(wid==0){
        float m = sred[lid];
#pragma unroll
        for(int off=16;off;off>>=1) m = fmaxf(m, __shfl_xor_sync(0xFFFFFFFFu, m, off));
        if(lid==0) sred[0]=m;
    }
    __syncthreads();
    float bm = sred[0];
    __syncthreads();

    float e = expf(v-bm);
    float sm = e;
#pragma unroll
    for(int off=16;off;off>>=1) sm += __shfl_xor_sync(0xFFFFFFFFu, sm, off);
    if(lid==0) sred[wid]=sm;
    __syncthreads();
    if(wid==0){
        float t = sred[lid];
#pragma unroll
        for(int off=16;off;off>>=1) t += __shfl_xor_sync(0xFFFFFFFFu, t, off);
        if(lid==0) sred[0]=t;
    }
    __syncthreads();
    float lse = bm + logf(sred[0]);

    out[(size_t)b*FF + o] = v - lse;
}

// ============================================================================
extern "C" void kernel_launch(void* const* d_in, const int* in_sizes, int n_in,
                              void* d_out, int out_size){
    const float* x   = (const float*)d_in[0];
    const float* adj = (const float*)d_in[1];
    const float* W   = (const float*)d_in[2];
    const float* a   = (const float*)d_in[3];
    const float* fcw = (const float*)d_in[4];
    const float* fcb = (const float*)d_in[5];
    float* out = (float*)d_out;

    cudaFuncSetAttribute(k1_wh, cudaFuncAttributeMaxDynamicSharedMemorySize, K1_SMEM);
    cudaFuncSetAttribute(k3_fc, cudaFuncAttributeMaxDynamicSharedMemorySize, K3_SMEM);

    k1_wh <<<HH*BB, 256, K1_SMEM>>>(x, W, adj, a);
    k3_fc <<<256, 256, K3_SMEM>>>(fcw);
    k4_out<<<BB, 1024>>>(fcb, out);
}